// round 7
// baseline (speedup 1.0000x reference)
#include <cuda_runtime.h>
#include <math.h>
#include <float.h>

#define B 8
#define H 480
#define W 640
#define HW (H*W)
#define TOPK 500
#define NKP (B*TOPK)
#define CAP 131072

#define KXY_OFF 0
#define DESC_OFF (NKP*2)
#define KPS_OFF (DESC_OFF + NKP*64)
#define DISP_OFF (KPS_OFF + NKP)

typedef unsigned long long ull;

// ---------------- device scratch ----------------
__device__ float g_cval[B*CAP];
__device__ int   g_cidx[B*CAP];
__device__ int   g_cnt[B];          // zero at load; re-zeroed by select (replay-safe)
__device__ int   g_topk[NKP];

__device__ __forceinline__ float fmax5(float a, float b, float c, float d, float e) {
    return fmaxf(fmaxf(fmaxf(a, b), fmaxf(c, d)), e);
}

// ============================================================================
// Bit-column NMS. One warp = 32-col lane span (16 output cols) x 40 output
// rows (60 streamed rows; row r <-> bit r of a 64-bit column mask).
// No shared memory, no barriers. Strips: 40 x-strips * 12 y-tiles * 8 batches
// = 3840 warps.
// ============================================================================

// stage 1: M = (s == maxpool5x5(s)); valid for all 32 lanes, bits [2,58)
__device__ __forceinline__ ull stage_one(const float* __restrict__ sb,
                                         int gy0, int gx_c, int lane) {
    ull M = 0ull;
    float h[5], c[5];
    #pragma unroll
    for (int j = 0; j < 5; j++) { h[j] = 0.f; c[j] = 0.f; }
    int gx_a = gx_c - 2, gx_b = gx_c + 2;
    bool ina = ((unsigned)gx_a < W), inb = ((unsigned)gx_b < W);
    for (int rr5 = 0; rr5 < 60; rr5 += 5) {
        #pragma unroll
        for (int j = 0; j < 5; j++) {
            int rr = rr5 + j;
            int gy = gy0 + rr;
            bool iny = ((unsigned)gy < H);
            float va = (iny && ina) ? sb[gy*W + gx_a] : 0.f;
            float vb = (iny && inb) ? sb[gy*W + gx_b] : 0.f;
            float d1 = __shfl_down_sync(~0u, va, 1);
            float d2 = __shfl_down_sync(~0u, va, 2);
            float d3 = __shfl_down_sync(~0u, va, 3);
            float u1 = __shfl_up_sync(~0u, vb, 1);
            float u2 = __shfl_up_sync(~0u, vb, 2);
            float u3 = __shfl_up_sync(~0u, vb, 3);
            float wl1 = (lane == 31) ? u3 : d1;   // col-1
            float ctr = (lane >= 30) ? u2 : d2;   // col
            float wr1 = (lane == 0)  ? d3 : u1;   // col+1
            h[j] = fmax5(va, wl1, ctr, wr1, vb);
            c[j] = ctr;
            if (rr >= 4) {
                float vm = fmaxf(fmaxf(fmaxf(h[0],h[1]), fmaxf(h[2],h[3])), h[4]);
                float cc = c[(j+3)%5];
                if (cc == vm) M |= 1ull << (rr - 2);
            }
        }
    }
    return M;
}

// suppression mask: 5x5-window OR of mask bits (vertical via shifts,
// horizontal via lane shuffles). Valid lanes shrink by 2 each side.
__device__ __forceinline__ ull suppmask(ull m) {
    ull v = (m << 2) | (m << 1) | m | (m >> 1) | (m >> 2);
    ull l1 = __shfl_up_sync(~0u, v, 1);
    ull l2 = __shfl_up_sync(~0u, v, 2);
    ull r1 = __shfl_down_sync(~0u, v, 1);
    ull r2 = __shfl_down_sync(~0u, v, 2);
    return v | l1 | l2 | r1 | r2;
}

// masked stage: NEW = (SS == maxpool5x5(SS)) & ~SMK, SS = SMK-bit ? 0 : s.
// Valid lanes shrink by 2 vs SMK validity; bits [4,56).
__device__ __forceinline__ ull stage_masked(const float* __restrict__ sb,
                                            int gy0, int gx_c, ull SMK) {
    ull NEW = 0ull;
    float h[5], c[5];
    #pragma unroll
    for (int j = 0; j < 5; j++) { h[j] = 0.f; c[j] = 0.f; }
    bool inx = ((unsigned)gx_c < W);
    for (int rr5 = 0; rr5 < 60; rr5 += 5) {
        #pragma unroll
        for (int j = 0; j < 5; j++) {
            int rr = rr5 + j;
            int gy = gy0 + rr;
            float v = (inx && (unsigned)gy < H) ? sb[gy*W + gx_c] : 0.f;
            float vss = ((SMK >> rr) & 1ull) ? 0.f : v;
            float wl2 = __shfl_up_sync(~0u, vss, 2);
            float wl1 = __shfl_up_sync(~0u, vss, 1);
            float wr1 = __shfl_down_sync(~0u, vss, 1);
            float wr2 = __shfl_down_sync(~0u, vss, 2);
            h[j] = fmax5(wl2, wl1, vss, wr1, wr2);
            c[j] = vss;
            if (rr >= 4) {
                float vm = fmaxf(fmaxf(fmaxf(h[0],h[1]), fmaxf(h[2],h[3])), h[4]);
                float cc = c[(j+3)%5];
                int cr = rr - 2;
                bool sup = (SMK >> cr) & 1ull;
                if (cc == vm && !sup) NEW |= 1ull << cr;
            }
        }
    }
    return NEW;
}

__global__ __launch_bounds__(256) void nms_kernel(const float* __restrict__ s) {
    int lane = threadIdx.x & 31;
    int gw = blockIdx.x * 8 + (threadIdx.x >> 5);   // 0..3839
    int b = gw / 480, rem = gw - b*480;
    int ty = rem / 40, sx = rem - ty*40;
    int gy0 = ty*40 - 10;
    int gx_c = sx*16 - 8 + lane;
    const float* sb = s + (size_t)b*HW;

    ull M1   = stage_one(sb, gy0, gx_c, lane);          // lanes [0,32), bits [2,58)
    ull SMK2 = suppmask(M1);                            // lanes [2,30), bits [4,56)
    ull Mf   = M1 | stage_masked(sb, gy0, gx_c, SMK2);  // lanes [4,28), bits [2,58)
    ull SMK4 = suppmask(Mf);                            // lanes [6,26), bits [8,52)
    ull Fin  = (Mf | stage_masked(sb, gy0, gx_c, SMK4)) // lanes [8,24)
             & (((1ull << 50) - 1) ^ ((1ull << 10) - 1));  // bits [10,50)

    if (lane >= 8 && lane < 24 && gx_c >= 3 && gx_c < W-2) {
        while (Fin) {
            int cr = __ffsll(Fin) - 1;
            Fin &= Fin - 1;
            int gy = gy0 + cr;
            if (gy >= 3 && gy < H-2) {
                int pos = atomicAdd(&g_cnt[b], 1);
                if (pos < CAP) {
                    g_cval[b*CAP + pos] = sb[gy*W + gx_c];
                    g_cidx[b*CAP + pos] = gy*W + gx_c;
                }
            }
        }
    }
}

// ============================================================================
// per-batch top-500: 3-level radix threshold + rank placement; re-zeroes g_cnt
// ============================================================================
__global__ __launch_bounds__(1024) void select_kernel() {
    __shared__ unsigned hist[2048];
    __shared__ unsigned gsum[64];
    __shared__ unsigned sel_key[1024];
    __shared__ int      sel_idx[1024];
    __shared__ int s_bsel, s_need, s_cnt;

    int b = blockIdx.x, tid = threadIdx.x;
    int lane = tid & 31, wid = tid >> 5;
    int n = min(g_cnt[b], CAP);
    __syncthreads();                     // all reads of g_cnt[b] complete ...
    if (tid == 0) g_cnt[b] = 0;          // ... before the reset (replay-safe)
    const float* vals = g_cval + b*CAP;
    const int*   idxs = g_cidx + b*CAP;

    unsigned prefix = 0;
    int need = TOPK;
    for (int level = 0; level < 3; level++) {
        int nbins = (level == 2) ? 1024 : 2048;
        for (int i = tid; i < nbins; i += 1024) hist[i] = 0;
        __syncthreads();
        for (int i = tid; i < n; i += 1024) {
            unsigned key = __float_as_uint(vals[i]);
            unsigned bin; bool ok;
            if (level == 0)      { ok = true;                  bin = key >> 21; }
            else if (level == 1) { ok = (key >> 21) == prefix; bin = (key >> 10) & 0x7FF; }
            else                 { ok = (key >> 10) == prefix; bin = key & 0x3FF; }
            if (ok) atomicAdd(&hist[bin], 1);
        }
        __syncthreads();
        {
            unsigned v = hist[tid];
            #pragma unroll
            for (int o = 16; o > 0; o >>= 1) v += __shfl_down_sync(~0u, v, o);
            if (lane == 0) gsum[wid] = v;
            if (nbins == 2048) {
                unsigned v2 = hist[tid + 1024];
                #pragma unroll
                for (int o = 16; o > 0; o >>= 1) v2 += __shfl_down_sync(~0u, v2, o);
                if (lane == 0) gsum[32 + wid] = v2;
            }
        }
        __syncthreads();
        if (wid == 0) {
            int ng = nbins >> 5;
            unsigned g0 = gsum[lane];
            unsigned g1 = (ng == 64) ? gsum[32 + lane] : 0u;
            unsigned s1 = g1;
            #pragma unroll
            for (int o = 1; o < 32; o <<= 1) { unsigned t = __shfl_down_sync(~0u, s1, o); if (lane + o < 32) s1 += t; }
            unsigned tot1 = __shfl_sync(~0u, s1, 0);
            unsigned s0 = g0;
            #pragma unroll
            for (int o = 1; o < 32; o <<= 1) { unsigned t = __shfl_down_sync(~0u, s0, o); if (lane + o < 32) s0 += t; }
            s0 += tot1;
            unsigned b0 = __ballot_sync(~0u, s0 >= (unsigned)need);
            unsigned b1 = __ballot_sync(~0u, (ng == 64) && (s1 >= (unsigned)need));
            int gstar; unsigned suf_after;
            if (b1) {
                int j = 31 - __clz(b1);
                gstar = 32 + j;
                suf_after = (j == 31) ? 0u : __shfl_sync(~0u, s1, j + 1);
            } else {
                gstar = 31 - __clz(b0);
                suf_after = (gstar == 31) ? tot1 : __shfl_sync(~0u, s0, gstar + 1);
            }
            int need_g = need - (int)suf_after;
            unsigned hs = hist[gstar*32 + lane];
            #pragma unroll
            for (int o = 1; o < 32; o <<= 1) { unsigned t = __shfl_down_sync(~0u, hs, o); if (lane + o < 32) hs += t; }
            unsigned bb = __ballot_sync(~0u, hs >= (unsigned)need_g);
            int bstar = 31 - __clz(bb);
            unsigned bsuf = (bstar == 31) ? 0u : __shfl_sync(~0u, hs, bstar + 1);
            if (lane == 0) { s_bsel = gstar*32 + bstar; s_need = need_g - (int)bsuf; }
        }
        __syncthreads();
        if (level == 0)      prefix = (unsigned)s_bsel;
        else if (level == 1) prefix = (prefix << 11) | (unsigned)s_bsel;
        else                 prefix = (prefix << 10) | (unsigned)s_bsel;
        need = s_need;
        __syncthreads();
    }
    unsigned T = prefix;

    if (tid == 0) s_cnt = 0;
    __syncthreads();
    for (int i = tid; i < n; i += 1024) {
        unsigned key = __float_as_uint(vals[i]);
        if (key >= T) {
            int p = atomicAdd(&s_cnt, 1);
            if (p < 1024) { sel_key[p] = key; sel_idx[p] = idxs[i]; }
        }
    }
    __syncthreads();
    int cnt = min(s_cnt, 1024);
    if (tid < cnt) {
        unsigned ki = sel_key[tid];
        int ii = sel_idx[tid];
        int rank = 0;
        for (int j = 0; j < cnt; j++) {
            unsigned kj = sel_key[j];
            int ij = sel_idx[j];
            rank += (kj > ki) || (kj == ki && ij < ii);
        }
        if (rank < TOPK) g_topk[b*TOPK + rank] = ii;
    }
}

__device__ __forceinline__ float wmax(float v) {
    #pragma unroll
    for (int o = 16; o > 0; o >>= 1) v = fmaxf(v, __shfl_xor_sync(0xffffffffu, v, o));
    return v;
}

// ============================================================================
// fused patch refinement + descriptor sampling: 8 keypoints per 512-thr block
// ============================================================================
__global__ __launch_bounds__(512) void patch_desc_kernel(
        const float* __restrict__ s, const float* __restrict__ dmap,
        float* __restrict__ out) {
    __shared__ float spx[8], spy[8];
    __shared__ float part[16];
    int tid = threadIdx.x;
    int kbase = blockIdx.x * 8;
    int wid = tid >> 5, lane = tid & 31;

    // ---- phase 1: warps 0..7 each refine one keypoint ----
    if (wid < 8) {
        int gw = kbase + wid;
        int b = gw / TOPK;
        int p = g_topk[gw];
        int y = p / W, x = p - y*W;
        int ky = lane / 5, kx = lane - ky*5;
        float v = -FLT_MAX;
        if (lane < 25) v = s[(size_t)b*HW + (y + ky - 2)*W + (x + kx - 2)];
        float mx = wmax(v);
        float gxk = (float)(kx - 2), gyk = (float)(ky - 2);
        float e = (lane < 25) ? __expf((v - mx) * 10.f) : 0.f;
        float s0 = e, s1 = e*gxk, s2 = e*gyk, s3 = e*(gxk*gxk + gyk*gyk);
        #pragma unroll
        for (int o = 16; o > 0; o >>= 1) {
            s0 += __shfl_xor_sync(~0u, s0, o);
            s1 += __shfl_xor_sync(~0u, s1, o);
            s2 += __shfl_xor_sync(~0u, s2, o);
            s3 += __shfl_xor_sync(~0u, s3, o);
        }
        if (lane == 0) {
            float denom = s0 + 1e-12f;
            float inv = 1.f / denom;
            float xr = s1 * inv, yr = s2 * inv;
            float disp = (s3 - 2.f*xr*s1 - 2.f*yr*s2 + (xr*xr + yr*yr)*s0) * 0.25f * inv;
            float fx = (float)x + xr, fy = (float)y + yr;
            float gx = fx / (float)(W-1) * 2.f - 1.f;
            float gy = fy / (float)(H-1) * 2.f - 1.f;
            out[KXY_OFF + gw*2 + 0] = gx;
            out[KXY_OFF + gw*2 + 1] = gy;
            out[DISP_OFF + gw] = disp;

            float px = fminf(fmaxf((gx + 1.f) * 0.5f * (float)(W-1), 0.f), (float)(W-1));
            float py = fminf(fmaxf((gy + 1.f) * 0.5f * (float)(H-1), 0.f), (float)(H-1));
            spx[wid] = px; spy[wid] = py;
            int x0 = (int)floorf(px), y0 = (int)floorf(py);
            float wx = px - (float)x0, wy = py - (float)y0;
            int x1 = min(x0 + 1, W-1), y1 = min(y0 + 1, H-1);
            const float* sb = s + (size_t)b*HW;
            float v00 = sb[y0*W + x0], v01 = sb[y0*W + x1];
            float v10 = sb[y1*W + x0], v11 = sb[y1*W + x1];
            out[KPS_OFF + gw] = v00*(1.f-wx)*(1.f-wy) + v01*wx*(1.f-wy)
                              + v10*(1.f-wx)*wy       + v11*wx*wy;
        }
    }
    __syncthreads();

    // ---- phase 2: descriptor gather + L2 norm (64 threads / keypoint) ----
    int kl = tid >> 6;            // 0..7
    int c  = tid & 63;
    int g  = kbase + kl;
    int b  = g / TOPK;
    float px = spx[kl], py = spy[kl];
    int x0 = (int)floorf(px), y0 = (int)floorf(py);
    float wx = px - (float)x0, wy = py - (float)y0;
    int x1 = min(x0 + 1, W-1), y1 = min(y0 + 1, H-1);
    const float* base = dmap + ((size_t)b*64 + c) * (size_t)HW;
    float v00 = base[y0*W + x0], v01 = base[y0*W + x1];
    float v10 = base[y1*W + x0], v11 = base[y1*W + x1];
    float d = v00*(1.f-wx)*(1.f-wy) + v01*wx*(1.f-wy)
            + v10*(1.f-wx)*wy       + v11*wx*wy;

    float ss = d * d;
    #pragma unroll
    for (int o = 16; o > 0; o >>= 1) ss += __shfl_xor_sync(0xffffffffu, ss, o);
    if (lane == 0) part[wid] = ss;
    __syncthreads();
    float tot = part[2*kl] + part[2*kl + 1];
    float nrm = fmaxf(sqrtf(tot), 1e-12f);
    out[DESC_OFF + g*64 + c] = d / nrm;
}

extern "C" void kernel_launch(void* const* d_in, const int* in_sizes, int n_in,
                              void* d_out, int out_size) {
    const float* scores = (const float*)d_in[0];
    const float* descs  = (const float*)d_in[1];
    float* out = (float*)d_out;

    nms_kernel<<<480, 256>>>(scores);
    select_kernel<<<B, 1024>>>();
    patch_desc_kernel<<<NKP/8, 512>>>(scores, descs, out);
}

// round 9
// speedup vs baseline: 1.8561x; 1.8561x over previous
#include <cuda_runtime.h>
#include <math.h>
#include <float.h>

#define B 8
#define H 480
#define W 640
#define HW (H*W)
#define TOPK 500
#define NKP (B*TOPK)
#define CAP 131072

#define KXY_OFF 0
#define DESC_OFF (NKP*2)
#define KPS_OFF (DESC_OFF + NKP*64)
#define DISP_OFF (KPS_OFF + NKP)

// ---------------- device scratch ----------------
__device__ float g_cval[B*CAP];
__device__ int   g_cidx[B*CAP];
__device__ int   g_cnt[B];          // zero at load; re-zeroed by select (replay-safe)
__device__ int   g_topk[NKP];

// ============================================================================
// Fused NMS (R3-proven): 32x32 output tile, radius-10 halo -> 52 rows x 56
// padded cols (tile col c at sc = c+2). float4 scores, byte-packed masks.
// ============================================================================
#define WP 56

__device__ __forceinline__ float4 f4max(float4 a, float4 b) {
    return make_float4(fmaxf(a.x,b.x), fmaxf(a.y,b.y), fmaxf(a.z,b.z), fmaxf(a.w,b.w));
}
__device__ __forceinline__ float fmax5(float a, float b, float c, float d, float e) {
    return fmaxf(fmaxf(fmaxf(a, b), fmaxf(c, d)), e);
}

__global__ __launch_bounds__(256) void nms_kernel(const float* __restrict__ s) {
    __shared__ __align__(16) float sT[52*WP];
    __shared__ __align__(16) float SS[52*WP];
    __shared__ __align__(16) float TF[52*WP];
    __shared__ __align__(4) unsigned char M  [52*WP];
    __shared__ __align__(4) unsigned char SMK[52*WP];
    __shared__ __align__(4) unsigned char TU [52*WP];

    int b = blockIdx.z, tid = threadIdx.x;
    int gx0 = blockIdx.x*32 - 10, gy0 = blockIdx.y*32 - 10;
    const float* sp = s + (size_t)b*HW;

    for (int i = tid; i < 52*WP; i += 256) {
        int r = i / WP, sc = i - r*WP;
        int gy = gy0 + r, gx = gx0 + sc - 2;
        sT[i] = (gy >= 0 && gy < H && gx >= 0 && gx < W) ? sp[gy*W + gx] : 0.f;
    }
    __syncthreads();

#define F4(A, r, cb)  (*(const float4*)&A[(r)*WP + (cb)])
#define F4W(A, r, cb) (*(float4*)&A[(r)*WP + (cb)])
#define U32(A, r, cb)  (*(const unsigned*)&A[(r)*WP + (cb)])
#define U32W(A, r, cb) (*(unsigned*)&A[(r)*WP + (cb)])

#define VPASS_F(SRC, R0, NR, CB0, NC)                                         \
    for (int i = tid; i < (NR)*(NC); i += 256) {                              \
        int q = i/(NC); int r = (R0)+q; int cb = (CB0) + 4*(i - q*(NC));      \
        float4 v = f4max(f4max(F4(SRC,r-2,cb), F4(SRC,r-1,cb)),               \
                         f4max(F4(SRC,r+1,cb), F4(SRC,r+2,cb)));              \
        F4W(TF,r,cb) = f4max(v, F4(SRC,r,cb));                                \
    }

#define HWIN(r, cb, o0, o1, o2, o3)                                           \
    float4 L = F4(TF,r,cb-4), Md = F4(TF,r,cb), R = F4(TF,r,cb+4);            \
    float o0 = fmax5(L.z, L.w, Md.x, Md.y, Md.z);                             \
    float o1 = fmax5(L.w, Md.x, Md.y, Md.z, Md.w);                            \
    float o2 = fmax5(Md.x, Md.y, Md.z, Md.w, R.x);                            \
    float o3 = fmax5(Md.y, Md.z, Md.w, R.x, R.y);

    // ---- stage 1: M = (s == max5(s)) ----
    VPASS_F(sT, 2, 48, 0, 14)
    __syncthreads();
    for (int i = tid; i < 48*12; i += 256) {
        int q = i/12; int r = 2+q; int cb = 4 + 4*(i - q*12);
        HWIN(r, cb, o0, o1, o2, o3)
        float4 t = F4(sT,r,cb);
        unsigned m = (t.x==o0 ? 1u:0u) | (t.y==o1 ? 0x100u:0u)
                   | (t.z==o2 ? 0x10000u:0u) | (t.w==o3 ? 0x1000000u:0u);
        U32W(M,r,cb) = m;
    }
    __syncthreads();

#define VPASS_U(R0, NR, CB0, NC)                                              \
    for (int i = tid; i < (NR)*(NC); i += 256) {                              \
        int q = i/(NC); int r = (R0)+q; int cb = (CB0) + 4*(i - q*(NC));      \
        U32W(TU,r,cb) = U32(M,r-2,cb)|U32(M,r-1,cb)|U32(M,r,cb)               \
                       |U32(M,r+1,cb)|U32(M,r+2,cb);                          \
    }

#define HOR_U(r, cb, any)                                                     \
    unsigned pv = U32(TU,r,cb-4), md = U32(TU,r,cb), nx = U32(TU,r,cb+4);     \
    unsigned any = md | __funnelshift_r(md,nx,8) | __funnelshift_r(md,nx,16)  \
                      | __funnelshift_l(pv,md,8) | __funnelshift_l(pv,md,16);

#define SUPP(R0, NR, CB0, NC)                                                 \
    for (int i = tid; i < (NR)*(NC); i += 256) {                              \
        int q = i/(NC); int r = (R0)+q; int cb = (CB0) + 4*(i - q*(NC));      \
        HOR_U(r, cb, any)                                                     \
        U32W(SMK,r,cb) = any;                                                 \
        float4 t = F4(sT,r,cb); float4 ss;                                    \
        ss.x = (any & 0xFFu)        ? 0.f : t.x;                              \
        ss.y = (any & 0xFF00u)      ? 0.f : t.y;                              \
        ss.z = (any & 0xFF0000u)    ? 0.f : t.z;                              \
        ss.w = (any & 0xFF000000u)  ? 0.f : t.w;                              \
        F4W(SS,r,cb) = ss;                                                    \
    }

    // ---- stage 2 ----
    VPASS_U(4, 44, 4, 12)
    __syncthreads();
    SUPP(4, 44, 4, 12)
    __syncthreads();

    // ---- stage 3: M |= (SS == max5(SS)) & !SMK ----
    VPASS_F(SS, 6, 40, 4, 12)
    __syncthreads();
    for (int i = tid; i < 40*10; i += 256) {
        int q = i/10; int r = 6+q; int cb = 8 + 4*(i - q*10);
        HWIN(r, cb, o0, o1, o2, o3)
        float4 ss = F4(SS,r,cb);
        unsigned sm = U32(SMK,r,cb);
        unsigned add = 0;
        if (ss.x==o0 && !(sm & 0xFFu))       add |= 1u;
        if (ss.y==o1 && !(sm & 0xFF00u))     add |= 0x100u;
        if (ss.z==o2 && !(sm & 0xFF0000u))   add |= 0x10000u;
        if (ss.w==o3 && !(sm & 0xFF000000u)) add |= 0x1000000u;
        if (add) U32W(M,r,cb) = U32(M,r,cb) | add;
    }
    __syncthreads();

    // ---- stage 4 ----
    VPASS_U(8, 36, 8, 10)
    __syncthreads();
    SUPP(8, 36, 8, 10)
    __syncthreads();

    // ---- stage 5 + border + compaction ----
    VPASS_F(SS, 10, 32, 8, 10)
    __syncthreads();
    for (int i = tid; i < 32*8; i += 256) {
        int q = i/8; int r = 10+q; int cb = 12 + 4*(i - q*8);
        HWIN(r, cb, o0, o1, o2, o3)
        float4 ss = F4(SS,r,cb);
        unsigned sm = U32(SMK,r,cb);
        unsigned mm = U32(M,r,cb);
        float om[4] = {o0, o1, o2, o3};
        float sv[4] = {ss.x, ss.y, ss.z, ss.w};
        #pragma unroll
        for (int j = 0; j < 4; j++) {
            int fin = ((mm >> (8*j)) & 0xFFu)
                    | ((sv[j] == om[j]) && !((sm >> (8*j)) & 0xFFu));
            if (fin) {
                int gy = gy0 + r, gx = gx0 + cb + j - 2;
                if (gy >= 3 && gy < H-2 && gx >= 3 && gx < W-2) {
                    int pos = atomicAdd(&g_cnt[b], 1);
                    if (pos < CAP) {
                        g_cval[b*CAP + pos] = sT[r*WP + cb + j];
                        g_cidx[b*CAP + pos] = gy*W + gx;
                    }
                }
            }
        }
    }
}

// ============================================================================
// per-batch top-500: 3-level radix threshold + rank placement; re-zeroes g_cnt
// ============================================================================
__global__ __launch_bounds__(1024) void select_kernel() {
    __shared__ unsigned hist[2048];
    __shared__ unsigned gsum[64];
    __shared__ unsigned sel_key[1024];
    __shared__ int      sel_idx[1024];
    __shared__ int s_bsel, s_need, s_cnt;

    int b = blockIdx.x, tid = threadIdx.x;
    int lane = tid & 31, wid = tid >> 5;
    int n = min(g_cnt[b], CAP);
    __syncthreads();                     // all reads of g_cnt[b] complete ...
    if (tid == 0) g_cnt[b] = 0;          // ... before the reset (replay-safe)
    const float* vals = g_cval + b*CAP;
    const int*   idxs = g_cidx + b*CAP;

    unsigned prefix = 0;
    int need = TOPK;
    for (int level = 0; level < 3; level++) {
        int nbins = (level == 2) ? 1024 : 2048;
        for (int i = tid; i < nbins; i += 1024) hist[i] = 0;
        __syncthreads();
        for (int i = tid; i < n; i += 1024) {
            unsigned key = __float_as_uint(vals[i]);
            unsigned bin; bool ok;
            if (level == 0)      { ok = true;                  bin = key >> 21; }
            else if (level == 1) { ok = (key >> 21) == prefix; bin = (key >> 10) & 0x7FF; }
            else                 { ok = (key >> 10) == prefix; bin = key & 0x3FF; }
            if (ok) atomicAdd(&hist[bin], 1);
        }
        __syncthreads();
        {
            unsigned v = hist[tid];
            #pragma unroll
            for (int o = 16; o > 0; o >>= 1) v += __shfl_down_sync(~0u, v, o);
            if (lane == 0) gsum[wid] = v;
            if (nbins == 2048) {
                unsigned v2 = hist[tid + 1024];
                #pragma unroll
                for (int o = 16; o > 0; o >>= 1) v2 += __shfl_down_sync(~0u, v2, o);
                if (lane == 0) gsum[32 + wid] = v2;
            }
        }
        __syncthreads();
        if (wid == 0) {
            int ng = nbins >> 5;
            unsigned g0 = gsum[lane];
            unsigned g1 = (ng == 64) ? gsum[32 + lane] : 0u;
            unsigned s1 = g1;
            #pragma unroll
            for (int o = 1; o < 32; o <<= 1) { unsigned t = __shfl_down_sync(~0u, s1, o); if (lane + o < 32) s1 += t; }
            unsigned tot1 = __shfl_sync(~0u, s1, 0);
            unsigned s0 = g0;
            #pragma unroll
            for (int o = 1; o < 32; o <<= 1) { unsigned t = __shfl_down_sync(~0u, s0, o); if (lane + o < 32) s0 += t; }
            s0 += tot1;
            unsigned b0 = __ballot_sync(~0u, s0 >= (unsigned)need);
            unsigned b1 = __ballot_sync(~0u, (ng == 64) && (s1 >= (unsigned)need));
            int gstar; unsigned suf_after;
            if (b1) {
                int j = 31 - __clz(b1);
                gstar = 32 + j;
                suf_after = (j == 31) ? 0u : __shfl_sync(~0u, s1, j + 1);
            } else {
                gstar = 31 - __clz(b0);
                suf_after = (gstar == 31) ? tot1 : __shfl_sync(~0u, s0, gstar + 1);
            }
            int need_g = need - (int)suf_after;
            unsigned hs = hist[gstar*32 + lane];
            #pragma unroll
            for (int o = 1; o < 32; o <<= 1) { unsigned t = __shfl_down_sync(~0u, hs, o); if (lane + o < 32) hs += t; }
            unsigned bb = __ballot_sync(~0u, hs >= (unsigned)need_g);
            int bstar = 31 - __clz(bb);
            unsigned bsuf = (bstar == 31) ? 0u : __shfl_sync(~0u, hs, bstar + 1);
            if (lane == 0) { s_bsel = gstar*32 + bstar; s_need = need_g - (int)bsuf; }
        }
        __syncthreads();
        if (level == 0)      prefix = (unsigned)s_bsel;
        else if (level == 1) prefix = (prefix << 11) | (unsigned)s_bsel;
        else                 prefix = (prefix << 10) | (unsigned)s_bsel;
        need = s_need;
        __syncthreads();
    }
    unsigned T = prefix;

    if (tid == 0) s_cnt = 0;
    __syncthreads();
    for (int i = tid; i < n; i += 1024) {
        unsigned key = __float_as_uint(vals[i]);
        if (key >= T) {
            int p = atomicAdd(&s_cnt, 1);
            if (p < 1024) { sel_key[p] = key; sel_idx[p] = idxs[i]; }
        }
    }
    __syncthreads();
    int cnt = min(s_cnt, 1024);
    if (tid < cnt) {
        unsigned ki = sel_key[tid];
        int ii = sel_idx[tid];
        int rank = 0;
        for (int j = 0; j < cnt; j++) {
            unsigned kj = sel_key[j];
            int ij = sel_idx[j];
            rank += (kj > ki) || (kj == ki && ij < ii);
        }
        if (rank < TOPK) g_topk[b*TOPK + rank] = ii;
    }
}

__device__ __forceinline__ float wmax(float v) {
    #pragma unroll
    for (int o = 16; o > 0; o >>= 1) v = fmaxf(v, __shfl_xor_sync(0xffffffffu, v, o));
    return v;
}

// ============================================================================
// fused patch refinement + descriptor sampling: 8 keypoints per 512-thr block
// ============================================================================
__global__ __launch_bounds__(512) void patch_desc_kernel(
        const float* __restrict__ s, const float* __restrict__ dmap,
        float* __restrict__ out) {
    __shared__ float spx[8], spy[8];
    __shared__ float part[16];
    int tid = threadIdx.x;
    int kbase = blockIdx.x * 8;
    int wid = tid >> 5, lane = tid & 31;

    // ---- phase 1: warps 0..7 each refine one keypoint ----
    if (wid < 8) {
        int gw = kbase + wid;
        int b = gw / TOPK;
        int p = g_topk[gw];
        int y = p / W, x = p - y*W;
        int ky = lane / 5, kx = lane - ky*5;
        float v = -FLT_MAX;
        if (lane < 25) v = s[(size_t)b*HW + (y + ky - 2)*W + (x + kx - 2)];
        float mx = wmax(v);
        float gxk = (float)(kx - 2), gyk = (float)(ky - 2);
        float e = (lane < 25) ? __expf((v - mx) * 10.f) : 0.f;
        float s0 = e, s1 = e*gxk, s2 = e*gyk, s3 = e*(gxk*gxk + gyk*gyk);
        #pragma unroll
        for (int o = 16; o > 0; o >>= 1) {
            s0 += __shfl_xor_sync(~0u, s0, o);
            s1 += __shfl_xor_sync(~0u, s1, o);
            s2 += __shfl_xor_sync(~0u, s2, o);
            s3 += __shfl_xor_sync(~0u, s3, o);
        }
        if (lane == 0) {
            float denom = s0 + 1e-12f;
            float inv = 1.f / denom;
            float xr = s1 * inv, yr = s2 * inv;
            float disp = (s3 - 2.f*xr*s1 - 2.f*yr*s2 + (xr*xr + yr*yr)*s0) * 0.25f * inv;
            float fx = (float)x + xr, fy = (float)y + yr;
            float gx = fx / (float)(W-1) * 2.f - 1.f;
            float gy = fy / (float)(H-1) * 2.f - 1.f;
            out[KXY_OFF + gw*2 + 0] = gx;
            out[KXY_OFF + gw*2 + 1] = gy;
            out[DISP_OFF + gw] = disp;

            float px = fminf(fmaxf((gx + 1.f) * 0.5f * (float)(W-1), 0.f), (float)(W-1));
            float py = fminf(fmaxf((gy + 1.f) * 0.5f * (float)(H-1), 0.f), (float)(H-1));
            spx[wid] = px; spy[wid] = py;
            int x0 = (int)floorf(px), y0 = (int)floorf(py);
            float wx = px - (float)x0, wy = py - (float)y0;
            int x1 = min(x0 + 1, W-1), y1 = min(y0 + 1, H-1);
            const float* sb = s + (size_t)b*HW;
            float v00 = sb[y0*W + x0], v01 = sb[y0*W + x1];
            float v10 = sb[y1*W + x0], v11 = sb[y1*W + x1];
            out[KPS_OFF + gw] = v00*(1.f-wx)*(1.f-wy) + v01*wx*(1.f-wy)
                              + v10*(1.f-wx)*wy       + v11*wx*wy;
        }
    }
    __syncthreads();

    // ---- phase 2: descriptor gather + L2 norm (64 threads / keypoint) ----
    int kl = tid >> 6;            // 0..7
    int c  = tid & 63;
    int g  = kbase + kl;
    int b  = g / TOPK;
    float px = spx[kl], py = spy[kl];
    int x0 = (int)floorf(px), y0 = (int)floorf(py);
    float wx = px - (float)x0, wy = py - (float)y0;
    int x1 = min(x0 + 1, W-1), y1 = min(y0 + 1, H-1);
    const float* base = dmap + ((size_t)b*64 + c) * (size_t)HW;
    float v00 = base[y0*W + x0], v01 = base[y0*W + x1];
    float v10 = base[y1*W + x0], v11 = base[y1*W + x1];
    float d = v00*(1.f-wx)*(1.f-wy) + v01*wx*(1.f-wy)
            + v10*(1.f-wx)*wy       + v11*wx*wy;

    float ss = d * d;
    #pragma unroll
    for (int o = 16; o > 0; o >>= 1) ss += __shfl_xor_sync(0xffffffffu, ss, o);
    if (lane == 0) part[wid] = ss;
    __syncthreads();
    float tot = part[2*kl] + part[2*kl + 1];
    float nrm = fmaxf(sqrtf(tot), 1e-12f);
    out[DESC_OFF + g*64 + c] = d / nrm;
}

extern "C" void kernel_launch(void* const* d_in, const int* in_sizes, int n_in,
                              void* d_out, int out_size) {
    const float* scores = (const float*)d_in[0];
    const float* descs  = (const float*)d_in[1];
    float* out = (float*)d_out;

    nms_kernel<<<dim3(W/32, H/32, B), 256>>>(scores);
    select_kernel<<<B, 1024>>>();
    patch_desc_kernel<<<NKP/8, 512>>>(scores, descs, out);
}

// round 10
// speedup vs baseline: 2.4410x; 1.3152x over previous
#include <cuda_runtime.h>
#include <math.h>
#include <float.h>

#define B 8
#define H 480
#define W 640
#define HW (H*W)
#define TOPK 500
#define NKP (B*TOPK)
#define CAP 131072

#define KXY_OFF 0
#define DESC_OFF (NKP*2)
#define KPS_OFF (DESC_OFF + NKP*64)
#define DISP_OFF (KPS_OFF + NKP)

typedef unsigned long long ull;

// ---------------- device scratch ----------------
__device__ float g_cval[B*CAP];
__device__ int   g_cidx[B*CAP];
__device__ int   g_cnt[B];          // zero at load; re-zeroed by select (replay-safe)
__device__ int   g_topk[NKP];

// ============================================================================
// Fused NMS: 32x32 output tile, radius-10 halo -> 52 rows x 56 padded cols.
// Scores + vpass temp in float smem; masks bit-packed one ull per row
// (bit sc = smem col). SS recomputed inline from sT + mask bits.
// ============================================================================
#define WP 56

__device__ __forceinline__ float4 f4max(float4 a, float4 b) {
    return make_float4(fmaxf(a.x,b.x), fmaxf(a.y,b.y), fmaxf(a.z,b.z), fmaxf(a.w,b.w));
}
__device__ __forceinline__ float fmax5(float a, float b, float c, float d, float e) {
    return fmaxf(fmaxf(fmaxf(a, b), fmaxf(c, d)), e);
}
__device__ __forceinline__ float4 mask4(float4 t, unsigned bits) {
    t.x = (bits & 1u) ? 0.f : t.x;
    t.y = (bits & 2u) ? 0.f : t.y;
    t.z = (bits & 4u) ? 0.f : t.z;
    t.w = (bits & 8u) ? 0.f : t.w;
    return t;
}

__global__ __launch_bounds__(256) void nms_kernel(const float* __restrict__ s) {
    __shared__ __align__(16) float sT[52*WP];
    __shared__ __align__(16) float TF[52*WP];
    __shared__ ull Mb[52];
    __shared__ ull SMKb[52];

    int b = blockIdx.z, tid = threadIdx.x;
    int gx0 = blockIdx.x*32 - 10, gy0 = blockIdx.y*32 - 10;
    const float* sp = s + (size_t)b*HW;

    if (tid < 52) Mb[tid] = 0ull;

    bool interior = (gx0 >= 2) && (gx0 + 54 <= W) && (gy0 >= 0) && (gy0 + 52 <= H);
    if (interior) {
        for (int i = tid; i < 52*14; i += 256) {
            int r = i / 14, c4 = (i - (i/14)*14) * 4;
            *(float4*)&sT[r*WP + c4] =
                *(const float4*)&sp[(gy0 + r)*W + gx0 + c4 - 2];
        }
    } else {
        for (int i = tid; i < 52*WP; i += 256) {
            int r = i / WP, sc = i - r*WP;
            int gy = gy0 + r, gx = gx0 + sc - 2;
            sT[i] = (gy >= 0 && gy < H && gx >= 0 && gx < W) ? sp[gy*W + gx] : 0.f;
        }
    }
    __syncthreads();

#define F4(A, r, cb)  (*(const float4*)&A[(r)*WP + (cb)])
#define F4W(A, r, cb) (*(float4*)&A[(r)*WP + (cb)])

#define HWIN(r, cb, o0, o1, o2, o3)                                           \
    float4 L = F4(TF,r,(cb)-4), Md = F4(TF,r,cb), R = F4(TF,r,(cb)+4);        \
    float o0 = fmax5(L.z, L.w, Md.x, Md.y, Md.z);                             \
    float o1 = fmax5(L.w, Md.x, Md.y, Md.z, Md.w);                            \
    float o2 = fmax5(Md.x, Md.y, Md.z, Md.w, R.x);                            \
    float o3 = fmax5(Md.y, Md.z, Md.w, R.x, R.y);

    // ---- phase 1: vpass of raw scores, rows [2,50), all 14 chunks ----
    for (int i = tid; i < 48*14; i += 256) {
        int q = i/14; int r = 2+q; int cb = 4*(i - q*14);
        float4 v = f4max(f4max(F4(sT,r-2,cb), F4(sT,r-1,cb)),
                         f4max(F4(sT,r+1,cb), F4(sT,r+2,cb)));
        F4W(TF,r,cb) = f4max(v, F4(sT,r,cb));
    }
    __syncthreads();
    // ---- phase 2: hpass -> Mb, rows [2,50), cb 4..48 ----
    for (int i = tid; i < 48*12; i += 256) {
        int q = i/12; int r = 2+q; int cb = 4 + 4*(i - q*12);
        HWIN(r, cb, o0, o1, o2, o3)
        float4 t = F4(sT,r,cb);
        unsigned m = (t.x==o0 ? 1u:0u) | (t.y==o1 ? 2u:0u)
                   | (t.z==o2 ? 4u:0u) | (t.w==o3 ? 8u:0u);
        if (m) atomicOr(&Mb[r], (ull)m << cb);
    }
    __syncthreads();

    // ---- phase 3: suppression mask rows [4,48) (one thread per row) ----
    if (tid < 44) {
        int r = 4 + tid;
        ull v = Mb[r-2] | Mb[r-1] | Mb[r] | Mb[r+1] | Mb[r+2];
        SMKb[r] = v | (v<<1) | (v<<2) | (v>>1) | (v>>2);
    }
    __syncthreads();

    // ---- phase 4: vpass of SS (= masked sT), rows [6,46), cb 4..48 ----
    for (int i = tid; i < 40*12; i += 256) {
        int q = i/12; int r = 6+q; int cb = 4 + 4*(i - q*12);
        float4 acc = make_float4(-FLT_MAX,-FLT_MAX,-FLT_MAX,-FLT_MAX);
        #pragma unroll
        for (int dr = -2; dr <= 2; dr++) {
            int rr = r + dr;
            unsigned bits = (unsigned)((SMKb[rr] >> cb) & 0xFull);
            acc = f4max(acc, mask4(F4(sT,rr,cb), bits));
        }
        F4W(TF,r,cb) = acc;
    }
    __syncthreads();
    // ---- phase 5: hpass3 -> Mb |= new peaks, rows [6,46), cb 8..44 ----
    for (int i = tid; i < 40*10; i += 256) {
        int q = i/10; int r = 6+q; int cb = 8 + 4*(i - q*10);
        HWIN(r, cb, o0, o1, o2, o3)
        unsigned smk = (unsigned)((SMKb[r] >> cb) & 0xFull);
        float4 ssv = mask4(F4(sT,r,cb), smk);
        unsigned add = ((ssv.x==o0 && !(smk&1u)) ? 1u:0u)
                     | ((ssv.y==o1 && !(smk&2u)) ? 2u:0u)
                     | ((ssv.z==o2 && !(smk&4u)) ? 4u:0u)
                     | ((ssv.w==o3 && !(smk&8u)) ? 8u:0u);
        if (add) atomicOr(&Mb[r], (ull)add << cb);
    }
    __syncthreads();

    // ---- phase 6: suppression mask rows [8,44) ----
    if (tid < 36) {
        int r = 8 + tid;
        ull v = Mb[r-2] | Mb[r-1] | Mb[r] | Mb[r+1] | Mb[r+2];
        SMKb[r] = v | (v<<1) | (v<<2) | (v>>1) | (v>>2);
    }
    __syncthreads();

    // ---- phase 7: vpass of SS4, rows [10,42), cb 8..44 ----
    for (int i = tid; i < 32*10; i += 256) {
        int q = i/10; int r = 10+q; int cb = 8 + 4*(i - q*10);
        float4 acc = make_float4(-FLT_MAX,-FLT_MAX,-FLT_MAX,-FLT_MAX);
        #pragma unroll
        for (int dr = -2; dr <= 2; dr++) {
            int rr = r + dr;
            unsigned bits = (unsigned)((SMKb[rr] >> cb) & 0xFull);
            acc = f4max(acc, mask4(F4(sT,rr,cb), bits));
        }
        F4W(TF,r,cb) = acc;
    }
    __syncthreads();
    // ---- phase 8: final + border + compaction, rows [10,42), cb 12..40 ----
    for (int i = tid; i < 32*8; i += 256) {
        int q = i/8; int r = 10+q; int cb = 12 + 4*(i - q*8);
        HWIN(r, cb, o0, o1, o2, o3)
        unsigned smk = (unsigned)((SMKb[r] >> cb) & 0xFull);
        unsigned mm  = (unsigned)((Mb[r]   >> cb) & 0xFull);
        float4 ssv = mask4(F4(sT,r,cb), smk);
        unsigned fin = mm
                     | ((ssv.x==o0 && !(smk&1u)) ? 1u:0u)
                     | ((ssv.y==o1 && !(smk&2u)) ? 2u:0u)
                     | ((ssv.z==o2 && !(smk&4u)) ? 4u:0u)
                     | ((ssv.w==o3 && !(smk&8u)) ? 8u:0u);
        while (fin) {
            int j = __ffs(fin) - 1;
            fin &= fin - 1;
            int gy = gy0 + r, gx = gx0 + cb + j - 2;
            if (gy >= 3 && gy < H-2 && gx >= 3 && gx < W-2) {
                int pos = atomicAdd(&g_cnt[b], 1);
                if (pos < CAP) {
                    g_cval[b*CAP + pos] = sT[r*WP + cb + j];
                    g_cidx[b*CAP + pos] = gy*W + gx;
                }
            }
        }
    }
}

// ============================================================================
// per-batch top-500: 3-level radix threshold + rank placement; re-zeroes g_cnt
// ============================================================================
__global__ __launch_bounds__(1024) void select_kernel() {
    __shared__ unsigned hist[2048];
    __shared__ unsigned gsum[64];
    __shared__ unsigned sel_key[1024];
    __shared__ int      sel_idx[1024];
    __shared__ int s_bsel, s_need, s_cnt;

    int b = blockIdx.x, tid = threadIdx.x;
    int lane = tid & 31, wid = tid >> 5;
    int n = min(g_cnt[b], CAP);
    __syncthreads();                     // all reads of g_cnt[b] complete ...
    if (tid == 0) g_cnt[b] = 0;          // ... before the reset (replay-safe)
    const float* vals = g_cval + b*CAP;
    const int*   idxs = g_cidx + b*CAP;

    unsigned prefix = 0;
    int need = TOPK;
    for (int level = 0; level < 3; level++) {
        int nbins = (level == 2) ? 1024 : 2048;
        for (int i = tid; i < nbins; i += 1024) hist[i] = 0;
        __syncthreads();
        for (int i = tid; i < n; i += 1024) {
            unsigned key = __float_as_uint(vals[i]);
            unsigned bin; bool ok;
            if (level == 0)      { ok = true;                  bin = key >> 21; }
            else if (level == 1) { ok = (key >> 21) == prefix; bin = (key >> 10) & 0x7FF; }
            else                 { ok = (key >> 10) == prefix; bin = key & 0x3FF; }
            if (ok) atomicAdd(&hist[bin], 1);
        }
        __syncthreads();
        {
            unsigned v = hist[tid];
            #pragma unroll
            for (int o = 16; o > 0; o >>= 1) v += __shfl_down_sync(~0u, v, o);
            if (lane == 0) gsum[wid] = v;
            if (nbins == 2048) {
                unsigned v2 = hist[tid + 1024];
                #pragma unroll
                for (int o = 16; o > 0; o >>= 1) v2 += __shfl_down_sync(~0u, v2, o);
                if (lane == 0) gsum[32 + wid] = v2;
            }
        }
        __syncthreads();
        if (wid == 0) {
            int ng = nbins >> 5;
            unsigned g0 = gsum[lane];
            unsigned g1 = (ng == 64) ? gsum[32 + lane] : 0u;
            unsigned s1 = g1;
            #pragma unroll
            for (int o = 1; o < 32; o <<= 1) { unsigned t = __shfl_down_sync(~0u, s1, o); if (lane + o < 32) s1 += t; }
            unsigned tot1 = __shfl_sync(~0u, s1, 0);
            unsigned s0 = g0;
            #pragma unroll
            for (int o = 1; o < 32; o <<= 1) { unsigned t = __shfl_down_sync(~0u, s0, o); if (lane + o < 32) s0 += t; }
            s0 += tot1;
            unsigned b0 = __ballot_sync(~0u, s0 >= (unsigned)need);
            unsigned b1 = __ballot_sync(~0u, (ng == 64) && (s1 >= (unsigned)need));
            int gstar; unsigned suf_after;
            if (b1) {
                int j = 31 - __clz(b1);
                gstar = 32 + j;
                suf_after = (j == 31) ? 0u : __shfl_sync(~0u, s1, j + 1);
            } else {
                gstar = 31 - __clz(b0);
                suf_after = (gstar == 31) ? tot1 : __shfl_sync(~0u, s0, gstar + 1);
            }
            int need_g = need - (int)suf_after;
            unsigned hs = hist[gstar*32 + lane];
            #pragma unroll
            for (int o = 1; o < 32; o <<= 1) { unsigned t = __shfl_down_sync(~0u, hs, o); if (lane + o < 32) hs += t; }
            unsigned bb = __ballot_sync(~0u, hs >= (unsigned)need_g);
            int bstar = 31 - __clz(bb);
            unsigned bsuf = (bstar == 31) ? 0u : __shfl_sync(~0u, hs, bstar + 1);
            if (lane == 0) { s_bsel = gstar*32 + bstar; s_need = need_g - (int)bsuf; }
        }
        __syncthreads();
        if (level == 0)      prefix = (unsigned)s_bsel;
        else if (level == 1) prefix = (prefix << 11) | (unsigned)s_bsel;
        else                 prefix = (prefix << 10) | (unsigned)s_bsel;
        need = s_need;
        __syncthreads();
    }
    unsigned T = prefix;

    if (tid == 0) s_cnt = 0;
    __syncthreads();
    for (int i = tid; i < n; i += 1024) {
        unsigned key = __float_as_uint(vals[i]);
        if (key >= T) {
            int p = atomicAdd(&s_cnt, 1);
            if (p < 1024) { sel_key[p] = key; sel_idx[p] = idxs[i]; }
        }
    }
    __syncthreads();
    int cnt = min(s_cnt, 1024);
    if (tid < cnt) {
        unsigned ki = sel_key[tid];
        int ii = sel_idx[tid];
        int rank = 0;
        for (int j = 0; j < cnt; j++) {
            unsigned kj = sel_key[j];
            int ij = sel_idx[j];
            rank += (kj > ki) || (kj == ki && ij < ii);
        }
        if (rank < TOPK) g_topk[b*TOPK + rank] = ii;
    }
}

__device__ __forceinline__ float wmax(float v) {
    #pragma unroll
    for (int o = 16; o > 0; o >>= 1) v = fmaxf(v, __shfl_xor_sync(0xffffffffu, v, o));
    return v;
}

// ============================================================================
// fused patch refinement + descriptor sampling: 8 keypoints per 512-thr block
// ============================================================================
__global__ __launch_bounds__(512) void patch_desc_kernel(
        const float* __restrict__ s, const float* __restrict__ dmap,
        float* __restrict__ out) {
    __shared__ float spx[8], spy[8];
    __shared__ float part[16];
    int tid = threadIdx.x;
    int kbase = blockIdx.x * 8;
    int wid = tid >> 5, lane = tid & 31;

    // ---- phase 1: warps 0..7 each refine one keypoint ----
    if (wid < 8) {
        int gw = kbase + wid;
        int b = gw / TOPK;
        int p = g_topk[gw];
        int y = p / W, x = p - y*W;
        int ky = lane / 5, kx = lane - ky*5;
        float v = -FLT_MAX;
        if (lane < 25) v = s[(size_t)b*HW + (y + ky - 2)*W + (x + kx - 2)];
        float mx = wmax(v);
        float gxk = (float)(kx - 2), gyk = (float)(ky - 2);
        float e = (lane < 25) ? __expf((v - mx) * 10.f) : 0.f;
        float s0 = e, s1 = e*gxk, s2 = e*gyk, s3 = e*(gxk*gxk + gyk*gyk);
        #pragma unroll
        for (int o = 16; o > 0; o >>= 1) {
            s0 += __shfl_xor_sync(~0u, s0, o);
            s1 += __shfl_xor_sync(~0u, s1, o);
            s2 += __shfl_xor_sync(~0u, s2, o);
            s3 += __shfl_xor_sync(~0u, s3, o);
        }
        if (lane == 0) {
            float denom = s0 + 1e-12f;
            float inv = 1.f / denom;
            float xr = s1 * inv, yr = s2 * inv;
            float disp = (s3 - 2.f*xr*s1 - 2.f*yr*s2 + (xr*xr + yr*yr)*s0) * 0.25f * inv;
            float fx = (float)x + xr, fy = (float)y + yr;
            float gx = fx / (float)(W-1) * 2.f - 1.f;
            float gy = fy / (float)(H-1) * 2.f - 1.f;
            out[KXY_OFF + gw*2 + 0] = gx;
            out[KXY_OFF + gw*2 + 1] = gy;
            out[DISP_OFF + gw] = disp;

            float px = fminf(fmaxf((gx + 1.f) * 0.5f * (float)(W-1), 0.f), (float)(W-1));
            float py = fminf(fmaxf((gy + 1.f) * 0.5f * (float)(H-1), 0.f), (float)(H-1));
            spx[wid] = px; spy[wid] = py;
            int x0 = (int)floorf(px), y0 = (int)floorf(py);
            float wx = px - (float)x0, wy = py - (float)y0;
            int x1 = min(x0 + 1, W-1), y1 = min(y0 + 1, H-1);
            const float* sb = s + (size_t)b*HW;
            float v00 = sb[y0*W + x0], v01 = sb[y0*W + x1];
            float v10 = sb[y1*W + x0], v11 = sb[y1*W + x1];
            out[KPS_OFF + gw] = v00*(1.f-wx)*(1.f-wy) + v01*wx*(1.f-wy)
                              + v10*(1.f-wx)*wy       + v11*wx*wy;
        }
    }
    __syncthreads();

    // ---- phase 2: descriptor gather + L2 norm (64 threads / keypoint) ----
    int kl = tid >> 6;            // 0..7
    int c  = tid & 63;
    int g  = kbase + kl;
    int b  = g / TOPK;
    float px = spx[kl], py = spy[kl];
    int x0 = (int)floorf(px), y0 = (int)floorf(py);
    float wx = px - (float)x0, wy = py - (float)y0;
    int x1 = min(x0 + 1, W-1), y1 = min(y0 + 1, H-1);
    const float* base = dmap + ((size_t)b*64 + c) * (size_t)HW;
    float v00 = base[y0*W + x0], v01 = base[y0*W + x1];
    float v10 = base[y1*W + x0], v11 = base[y1*W + x1];
    float d = v00*(1.f-wx)*(1.f-wy) + v01*wx*(1.f-wy)
            + v10*(1.f-wx)*wy       + v11*wx*wy;

    float ss = d * d;
    #pragma unroll
    for (int o = 16; o > 0; o >>= 1) ss += __shfl_xor_sync(0xffffffffu, ss, o);
    if (lane == 0) part[wid] = ss;
    __syncthreads();
    float tot = part[2*kl] + part[2*kl + 1];
    float nrm = fmaxf(sqrtf(tot), 1e-12f);
    out[DESC_OFF + g*64 + c] = d / nrm;
}

extern "C" void kernel_launch(void* const* d_in, const int* in_sizes, int n_in,
                              void* d_out, int out_size) {
    const float* scores = (const float*)d_in[0];
    const float* descs  = (const float*)d_in[1];
    float* out = (float*)d_out;

    nms_kernel<<<dim3(W/32, H/32, B), 256>>>(scores);
    select_kernel<<<B, 1024>>>();
    patch_desc_kernel<<<NKP/8, 512>>>(scores, descs, out);
}